// round 16
// baseline (speedup 1.0000x reference)
#include <cuda_runtime.h>
#include <cuda_bf16.h>
#include <math.h>
#include <stdint.h>

#define TT 2048
#define DD 1024
#define NH 16
#define NKV 4
#define HD 64
#define NE 8
#define FF 2048
#define VV 32000
#define WIN 1024
#define NGLB 32
#define PP 136

// ---------------- scratch (device globals; allocation-free) ----------------
__device__ float g_x[TT * DD];
__device__ float g_h[TT * DD];
__device__ float g_q[TT * NH * HD];
__device__ float g_k[TT * NKV * HD];
__device__ float g_v[TT * NKV * HD];
__device__ float g_cos[TT * 32];
__device__ float g_sin[TT * 32];
__device__ float g_ubuf[NE * TT * FF];
__device__ float g_yslot[TT * 2 * DD];
__device__ float g_wslot[TT * 2];
__device__ int   g_idxl[NE * TT];
__device__ int   g_counts[NE];
__device__ float g_probsum[NE];
__device__ float g_aux;
// bf16 hi/lo planes (uint32 = packed bf16x2 along k-pairs)
__device__ uint32_t g_hhi[TT * DD / 2],  g_hlo[TT * DD / 2];    // rmsnorm out
__device__ uint32_t g_ahi[TT * DD / 2],  g_alo[TT * DD / 2];    // attn out
__device__ uint32_t g_abhi[NE * TT * FF / 2], g_ablo[NE * TT * FF / 2]; // moe act
__device__ uint32_t g_bqh[DD / 2 * NH * HD],  g_bql[DD / 2 * NH * HD];
__device__ uint32_t g_bkh[DD / 2 * NKV * HD], g_bkl[DD / 2 * NKV * HD];
__device__ uint32_t g_bvh[DD / 2 * NKV * HD], g_bvl[DD / 2 * NKV * HD];
__device__ uint32_t g_boh[NH * HD / 2 * DD],  g_bol[NH * HD / 2 * DD];
__device__ uint32_t g_buh[NE * DD / 2 * FF],  g_bul[NE * DD / 2 * FF];
__device__ uint32_t g_bgh[NE * DD / 2 * FF],  g_bgl[NE * DD / 2 * FF];
__device__ uint32_t g_bdh[NE * FF / 2 * DD],  g_bdl[NE * FF / 2 * DD];
__device__ uint32_t g_ebh[(size_t)VV * DD / 2], g_ebl[(size_t)VV * DD / 2];

// ---------------- helpers ----------------
__device__ __forceinline__ void split2(float x0, float x1, uint32_t& hi, uint32_t& lo) {
    __nv_bfloat162 h = __floats2bfloat162_rn(x0, x1);
    float h0 = __bfloat162float(h.x), h1 = __bfloat162float(h.y);
    __nv_bfloat162 l = __floats2bfloat162_rn(x0 - h0, x1 - h1);
    hi = *reinterpret_cast<uint32_t*>(&h);
    lo = *reinterpret_cast<uint32_t*>(&l);
}

__device__ __forceinline__ void mma16(float* c, uint32_t a0, uint32_t a1, uint32_t a2,
                                      uint32_t a3, uint32_t b0, uint32_t b1) {
    asm volatile(
        "mma.sync.aligned.m16n8k16.row.col.f32.bf16.bf16.f32 "
        "{%0,%1,%2,%3}, {%4,%5,%6,%7}, {%8,%9}, {%0,%1,%2,%3};"
        : "+f"(c[0]), "+f"(c[1]), "+f"(c[2]), "+f"(c[3])
        : "r"(a0), "r"(a1), "r"(a2), "r"(a3), "r"(b0), "r"(b1));
}

__device__ __forceinline__ void bf16_block_mma(float (*cacc)[4][4],
                                               const uint32_t* Ahs, const uint32_t* Als,
                                               const uint32_t* Bhs, const uint32_t* Bls,
                                               int lane, int wm, int wn) {
    int lr = lane >> 2, lc = lane & 3;
    #pragma unroll
    for (int kq = 0; kq < 16; kq += 8) {
        uint32_t bh0[4], bh1[4], bl0[4], bl1[4];
        #pragma unroll
        for (int nt = 0; nt < 4; nt++) {
            int n = wn + nt * 8 + lr;
            bh0[nt] = Bhs[(kq + lc) * PP + n];     bh1[nt] = Bhs[(kq + lc + 4) * PP + n];
            bl0[nt] = Bls[(kq + lc) * PP + n];     bl1[nt] = Bls[(kq + lc + 4) * PP + n];
        }
        #pragma unroll
        for (int mt = 0; mt < 4; mt++) {
            int m = wm + mt * 16 + lr;
            uint32_t ah0 = Ahs[(kq + lc) * PP + m],     ah1 = Ahs[(kq + lc) * PP + m + 8];
            uint32_t ah2 = Ahs[(kq + lc + 4) * PP + m], ah3 = Ahs[(kq + lc + 4) * PP + m + 8];
            uint32_t al0 = Als[(kq + lc) * PP + m],     al1 = Als[(kq + lc) * PP + m + 8];
            uint32_t al2 = Als[(kq + lc + 4) * PP + m], al3 = Als[(kq + lc + 4) * PP + m + 8];
            #pragma unroll
            for (int nt = 0; nt < 4; nt++) {
                mma16(cacc[mt][nt], ah0, ah1, ah2, ah3, bh0[nt], bh1[nt]);
                mma16(cacc[mt][nt], al0, al1, al2, al3, bh0[nt], bh1[nt]);
                mma16(cacc[mt][nt], ah0, ah1, ah2, ah3, bl0[nt], bl1[nt]);
            }
        }
    }
}

// ---------------- small kernels ----------------
__global__ void embed_kernel(const int* __restrict__ tok, const float* __restrict__ emb,
                             float* __restrict__ x) {
    int idx = blockIdx.x * 256 + threadIdx.x;
    int t = idx >> 10, d = idx & 1023;
    x[idx] = emb[(size_t)tok[t] * DD + d];
}

__global__ void rope_table_kernel() {
    int idx = blockIdx.x * 256 + threadIdx.x;
    int t = idx >> 5, i = idx & 31;
    float inv = 1.0f / powf(500000.0f, (float)(2 * i) * (1.0f / 64.0f));
    float ang = (float)t * inv;
    g_cos[idx] = cosf(ang);
    g_sin[idx] = sinf(ang);
}

// rmsnorm: fp32 out + bf16 hi/lo planes (packed d-pairs)
__global__ void rmsnorm_kernel(const float* __restrict__ x, const float* __restrict__ w,
                               float* __restrict__ o,
                               uint32_t* __restrict__ ohi, uint32_t* __restrict__ olo) {
    int t = blockIdx.x, tid = threadIdx.x;
    const float* xr = x + (size_t)t * DD;
    float ss = 0.f;
    for (int d = tid; d < DD; d += 256) { float v = xr[d]; ss += v * v; }
    #pragma unroll
    for (int off = 16; off; off >>= 1) ss += __shfl_down_sync(0xffffffffu, ss, off);
    __shared__ float sred[8];
    __shared__ float sinv;
    if ((tid & 31) == 0) sred[tid >> 5] = ss;
    __syncthreads();
    if (tid == 0) {
        float tot = 0.f;
        #pragma unroll
        for (int i = 0; i < 8; i++) tot += sred[i];
        sinv = rsqrtf(tot * (1.0f / DD) + 1.1920929e-07f);
    }
    __syncthreads();
    float inv = sinv;
    for (int d2 = tid; d2 < DD / 2; d2 += 256) {
        float a = xr[2 * d2] * inv * w[2 * d2];
        float b = xr[2 * d2 + 1] * inv * w[2 * d2 + 1];
        *(float2*)&o[(size_t)t * DD + 2 * d2] = make_float2(a, b);
        uint32_t h, l; split2(a, b, h, l);
        ohi[(size_t)t * (DD / 2) + d2] = h;
        olo[(size_t)t * (DD / 2) + d2] = l;
    }
}

// weight convert: fp32 [nmat][K][N] -> planes [nmat][K/2][N]
__global__ void convert_nn_kernel(const float* __restrict__ src,
                                  uint32_t* __restrict__ hi, uint32_t* __restrict__ lo,
                                  int K, int N, long total) {
    long idx = (long)blockIdx.x * 256 + threadIdx.x;
    if (idx >= total) return;
    long per = (long)(K / 2) * N;
    long mat = idx / per;
    long rem = idx - mat * per;
    int q = (int)(rem / N), n = (int)(rem % N);
    const float* s = src + (size_t)mat * K * N;
    float x0 = s[(size_t)(2 * q) * N + n];
    float x1 = s[(size_t)(2 * q + 1) * N + n];
    uint32_t h, l; split2(x0, x1, h, l);
    hi[idx] = h; lo[idx] = l;
}

// row convert: fp32 [R][2*K2] -> planes [R][K2]
__global__ void convert_rows_kernel(const float* __restrict__ src,
                                    uint32_t* __restrict__ hi, uint32_t* __restrict__ lo,
                                    int K2, long total) {
    long idx = (long)blockIdx.x * 256 + threadIdx.x;
    if (idx >= total) return;
    long r = idx / K2;
    int q = (int)(idx % K2);
    float2 v = *(const float2*)(src + (size_t)r * 2 * K2 + 2 * q);
    uint32_t h, l; split2(v.x, v.y, h, l);
    hi[idx] = h; lo[idx] = l;
}

// ---------------- flash attention (verified; epilogue -> planes) ----------------
__global__ void __launch_bounds__(128) attn_flash_kernel(const float* __restrict__ q,
                                                         const float* __restrict__ k,
                                                         const float* __restrict__ v) {
    int h = blockIdx.y;
    int qs = blockIdx.x * 128;
    int i = qs + threadIdx.x;
    int kvh = h >> 2;
    __shared__ float Ksh[32][64];
    __shared__ float Vsh[32][64];
    float qr[64];
    {
        const float* qrow = q + (size_t)i * (NH * HD) + h * HD;
        const float* ci = g_cos + i * 32;
        const float* si = g_sin + i * 32;
        #pragma unroll
        for (int d = 0; d < 32; d++) {
            float c = ci[d], s = si[d];
            float a = qrow[d], b = qrow[d + 32];
            qr[d]      = (a * c - b * s) * 0.125f;
            qr[d + 32] = (b * c + a * s) * 0.125f;
        }
    }
    float m = -1e30f, l = 0.f;
    float acc[64];
    #pragma unroll
    for (int d = 0; d < 64; d++) acc[d] = 0.f;

    for (int j0 = 0; j0 <= qs + 127; j0 += 32) {
        if (j0 >= NGLB && j0 + 31 < qs - WIN + 1) continue;
        for (int e = threadIdx.x; e < 32 * 64; e += 128) {
            int jj = e >> 6, d = e & 63;
            int j = j0 + jj;
            const float* kr = k + (size_t)j * (NKV * HD) + kvh * HD;
            float val;
            if (d < 32) {
                float c = g_cos[j * 32 + d], s = g_sin[j * 32 + d];
                val = kr[d] * c - kr[d + 32] * s;
            } else {
                int d2 = d - 32;
                float c = g_cos[j * 32 + d2], s = g_sin[j * 32 + d2];
                val = kr[d] * c + kr[d2] * s;
            }
            Ksh[jj][d] = val;
            Vsh[jj][d] = v[(size_t)j * (NKV * HD) + kvh * HD + d];
        }
        __syncthreads();
        float s[32];
        #pragma unroll
        for (int jj = 0; jj < 32; jj++) {
            float a = 0.f;
            #pragma unroll
            for (int d = 0; d < 64; d++) a += qr[d] * Ksh[jj][d];
            int j = j0 + jj;
            bool ok = (j <= i) && ((i - j) < WIN || j < NGLB);
            s[jj] = ok ? a : -1e30f;
        }
        float mt = -1e30f;
        #pragma unroll
        for (int jj = 0; jj < 32; jj++) mt = fmaxf(mt, s[jj]);
        if (mt > -1e29f) {
            float mn = fmaxf(m, mt);
            float f = __expf(m - mn);
            l *= f;
            #pragma unroll
            for (int d = 0; d < 64; d++) acc[d] *= f;
            #pragma unroll
            for (int jj = 0; jj < 32; jj++) {
                float pj = __expf(s[jj] - mn);
                l += pj;
                #pragma unroll
                for (int d = 0; d < 64; d++) acc[d] += pj * Vsh[jj][d];
            }
            m = mn;
        }
        __syncthreads();
    }
    float il = 1.0f / l;
    size_t base = (size_t)i * (DD / 2) + h * 32;
    #pragma unroll
    for (int j = 0; j < 32; j++) {
        uint32_t hh, ll;
        split2(acc[2 * j] * il, acc[2 * j + 1] * il, hh, ll);
        g_ahi[base + j] = hh;
        g_alo[base + j] = ll;
    }
}

// ---------------- GEMM staging macros ----------------
#define TB_PROLOG2                                                             \
    __shared__ uint32_t Ahs[16 * PP], Als[16 * PP], Bhs[16 * PP], Bls[16 * PP];\
    const int tid = threadIdx.x, lane = tid & 31, warp = tid >> 5;             \
    const int wm = (warp >> 2) * 64, wn = (warp & 3) * 32;                     \
    const int am = tid >> 1, aq = (tid & 1) * 8;                               \
    const int bqr = tid >> 4, bnc = (tid & 15) * 8;                            \
    float cacc[4][4][4];                                                       \
    _Pragma("unroll") for (int i = 0; i < 4; i++)                              \
        _Pragma("unroll") for (int j = 0; j < 4; j++)                          \
            _Pragma("unroll") for (int r = 0; r < 4; r++) cacc[i][j][r] = 0.f;

#define STAGE_ROWS(Sh, Sl, ph, pl, kq0)                                        \
    {                                                                          \
        uint4 h0 = *(const uint4*)((ph) + (kq0));                              \
        uint4 h1 = *(const uint4*)((ph) + (kq0) + 4);                          \
        uint4 l0 = *(const uint4*)((pl) + (kq0));                              \
        uint4 l1 = *(const uint4*)((pl) + (kq0) + 4);                          \
        Sh[(aq+0)*PP+am]=h0.x; Sh[(aq+1)*PP+am]=h0.y;                          \
        Sh[(aq+2)*PP+am]=h0.z; Sh[(aq+3)*PP+am]=h0.w;                          \
        Sh[(aq+4)*PP+am]=h1.x; Sh[(aq+5)*PP+am]=h1.y;                          \
        Sh[(aq+6)*PP+am]=h1.z; Sh[(aq+7)*PP+am]=h1.w;                          \
        Sl[(aq+0)*PP+am]=l0.x; Sl[(aq+1)*PP+am]=l0.y;                          \
        Sl[(aq+2)*PP+am]=l0.z; Sl[(aq+3)*PP+am]=l0.w;                          \
        Sl[(aq+4)*PP+am]=l1.x; Sl[(aq+5)*PP+am]=l1.y;                          \
        Sl[(aq+6)*PP+am]=l1.z; Sl[(aq+7)*PP+am]=l1.w;                          \
    }

#define STAGE_B_NN(Bh, Bl, N, n0, kq0)                                         \
    {                                                                          \
        const uint32_t* brh = (Bh) + (size_t)((kq0) + bqr) * (N) + (n0) + bnc; \
        const uint32_t* brl = (Bl) + (size_t)((kq0) + bqr) * (N) + (n0) + bnc; \
        *(uint4*)&Bhs[bqr*PP+bnc]   = *(const uint4*)brh;                      \
        *(uint4*)&Bhs[bqr*PP+bnc+4] = *(const uint4*)(brh + 4);                \
        *(uint4*)&Bls[bqr*PP+bnc]   = *(const uint4*)brl;                      \
        *(uint4*)&Bls[bqr*PP+bnc+4] = *(const uint4*)(brl + 4);                \
    }

// ---- generic NN with optional C += : A planes [M][K/2], B planes [K/2][N] ----
template <bool ADD>
__global__ void __launch_bounds__(256) tgemm_nn_kernel(const uint32_t* __restrict__ Ah,
                                                       const uint32_t* __restrict__ Al,
                                                       const uint32_t* __restrict__ Bh,
                                                       const uint32_t* __restrict__ Bl,
                                                       float* __restrict__ C,
                                                       int M, int N, int K) {
    const int m0 = blockIdx.y * 128, n0 = blockIdx.x * 128;
    TB_PROLOG2
    const int K2 = K >> 1;
    const uint32_t* arh = Ah + (size_t)(m0 + am) * K2 + aq;
    const uint32_t* arl = Al + (size_t)(m0 + am) * K2 + aq;
    for (int kq0 = 0; kq0 < K2; kq0 += 16) {
        STAGE_ROWS(Ahs, Als, arh, arl, kq0)
        STAGE_B_NN(Bh, Bl, N, n0, kq0)
        __syncthreads();
        bf16_block_mma(cacc, Ahs, Als, Bhs, Bls, lane, wm, wn);
        __syncthreads();
    }
    int lr = lane >> 2, lc = lane & 3;
    #pragma unroll
    for (int mt = 0; mt < 4; mt++) {
        int r0 = m0 + wm + mt * 16 + lr;
        #pragma unroll
        for (int nt = 0; nt < 4; nt++) {
            size_t c0 = (size_t)r0 * N + n0 + wn + nt * 8 + lc * 2;
            size_t c1 = (size_t)(r0 + 8) * N + n0 + wn + nt * 8 + lc * 2;
            if (ADD) {
                C[c0] += cacc[mt][nt][0]; C[c0 + 1] += cacc[mt][nt][1];
                C[c1] += cacc[mt][nt][2]; C[c1 + 1] += cacc[mt][nt][3];
            } else {
                C[c0] = cacc[mt][nt][0]; C[c0 + 1] = cacc[mt][nt][1];
                C[c1] = cacc[mt][nt][2]; C[c1 + 1] = cacc[mt][nt][3];
            }
        }
    }
}

// ---- NT: A planes [M][K/2], B planes [N][K/2] (lm_head) ----
__global__ void __launch_bounds__(256) tgemm_nt_kernel(const uint32_t* __restrict__ Ah,
                                                       const uint32_t* __restrict__ Al,
                                                       const uint32_t* __restrict__ Bh,
                                                       const uint32_t* __restrict__ Bl,
                                                       float* __restrict__ C,
                                                       int M, int N, int K) {
    const int m0 = blockIdx.y * 128, n0 = blockIdx.x * 128;
    TB_PROLOG2
    const int K2 = K >> 1;
    const uint32_t* arh = Ah + (size_t)(m0 + am) * K2 + aq;
    const uint32_t* arl = Al + (size_t)(m0 + am) * K2 + aq;
    const uint32_t* brh = Bh + (size_t)(n0 + am) * K2 + aq;
    const uint32_t* brl = Bl + (size_t)(n0 + am) * K2 + aq;
    for (int kq0 = 0; kq0 < K2; kq0 += 16) {
        STAGE_ROWS(Ahs, Als, arh, arl, kq0)
        STAGE_ROWS(Bhs, Bls, brh, brl, kq0)
        __syncthreads();
        bf16_block_mma(cacc, Ahs, Als, Bhs, Bls, lane, wm, wn);
        __syncthreads();
    }
    int lr = lane >> 2, lc = lane & 3;
    #pragma unroll
    for (int mt = 0; mt < 4; mt++) {
        int r0 = m0 + wm + mt * 16 + lr;
        #pragma unroll
        for (int nt = 0; nt < 4; nt++) {
            size_t c0 = (size_t)r0 * N + n0 + wn + nt * 8 + lc * 2;
            size_t c1 = (size_t)(r0 + 8) * N + n0 + wn + nt * 8 + lc * 2;
            C[c0] = cacc[mt][nt][0]; C[c0 + 1] = cacc[mt][nt][1];
            C[c1] = cacc[mt][nt][2]; C[c1 + 1] = cacc[mt][nt][3];
        }
    }
}

// ---- MoE up: gathered A plane rows; out fp32 g_ubuf ----
__global__ void __launch_bounds__(256) tmoe_up_kernel() {
    int e = blockIdx.z;
    int count = g_counts[e];
    int m0 = blockIdx.y * 128;
    if (m0 >= count) return;
    const int n0 = blockIdx.x * 128;
    TB_PROLOG2
    const uint32_t* Bh = g_buh + (size_t)e * (DD / 2) * FF;
    const uint32_t* Bl = g_bul + (size_t)e * (DD / 2) * FF;
    int gi = m0 + am;
    int token = (gi < count) ? (g_idxl[e * TT + gi] >> 1) : 0;
    const uint32_t* arh = g_hhi + (size_t)token * (DD / 2) + aq;
    const uint32_t* arl = g_hlo + (size_t)token * (DD / 2) + aq;
    for (int kq0 = 0; kq0 < DD / 2; kq0 += 16) {
        STAGE_ROWS(Ahs, Als, arh, arl, kq0)
        STAGE_B_NN(Bh, Bl, FF, n0, kq0)
        __syncthreads();
        bf16_block_mma(cacc, Ahs, Als, Bhs, Bls, lane, wm, wn);
        __syncthreads();
    }
    int lr = lane >> 2, lc = lane & 3;
    #pragma unroll
    for (int mt = 0; mt < 4; mt++) {
        int r0 = m0 + wm + mt * 16 + lr;
        #pragma unroll
        for (int nt = 0; nt < 4; nt++) {
            int cn = n0 + wn + nt * 8 + lc * 2;
            if (r0 < count) {
                size_t cb = ((size_t)e * TT + r0) * FF + cn;
                g_ubuf[cb] = cacc[mt][nt][0]; g_ubuf[cb + 1] = cacc[mt][nt][1];
            }
            if (r0 + 8 < count) {
                size_t cb = ((size_t)e * TT + r0 + 8) * FF + cn;
                g_ubuf[cb] = cacc[mt][nt][2]; g_ubuf[cb + 1] = cacc[mt][nt][3];
            }
        }
    }
}

// ---- MoE gate: epilogue silu(g)*ubuf -> act planes ----
__global__ void __launch_bounds__(256) tmoe_gate_kernel() {
    int e = blockIdx.z;
    int count = g_counts[e];
    int m0 = blockIdx.y * 128;
    if (m0 >= count) return;
    const int n0 = blockIdx.x * 128;
    TB_PROLOG2
    const uint32_t* Bh = g_bgh + (size_t)e * (DD / 2) * FF;
    const uint32_t* Bl = g_bgl + (size_t)e * (DD / 2) * FF;
    int gi = m0 + am;
    int token = (gi < count) ? (g_idxl[e * TT + gi] >> 1) : 0;
    const uint32_t* arh = g_hhi + (size_t)token * (DD / 2) + aq;
    const uint32_t* arl = g_hlo + (size_t)token * (DD / 2) + aq;
    for (int kq0 = 0; kq0 < DD / 2; kq0 += 16) {
        STAGE_ROWS(Ahs, Als, arh, arl, kq0)
        STAGE_B_NN(Bh, Bl, FF, n0, kq0)
        __syncthreads();
        bf16_block_mma(cacc, Ahs, Als, Bhs, Bls, lane, wm, wn);
        __syncthreads();
    }
    int lr = lane >> 2, lc = lane & 3;
    #pragma unroll
    for (int mt = 0; mt < 4; mt++) {
        int r0 = m0 + wm + mt * 16 + lr;
        #pragma unroll
        for (int nt = 0; nt < 4; nt++) {
            int cn = n0 + wn + nt * 8 + lc * 2;
            #pragma unroll
            for (int half = 0; half < 2; half++) {
                int row = r0 + half * 8;
                if (row < count) {
                    size_t ub = ((size_t)e * TT + row) * FF + cn;
                    float ga = cacc[mt][nt][half * 2];
                    float gb = cacc[mt][nt][half * 2 + 1];
                    float a0 = ga / (1.f + __expf(-ga)) * g_ubuf[ub];
                    float a1 = gb / (1.f + __expf(-gb)) * g_ubuf[ub + 1];
                    uint32_t h, l; split2(a0, a1, h, l);
                    size_t pb = ((size_t)e * TT + row) * (FF / 2) + cn / 2;
                    g_abhi[pb] = h; g_ablo[pb] = l;
                }
            }
        }
    }
}

// ---- MoE down: A act planes; weighted scatter to g_yslot ----
__global__ void __launch_bounds__(256) tmoe_down_kernel() {
    int e = blockIdx.z;
    int count = g_counts[e];
    int m0 = blockIdx.y * 128;
    if (m0 >= count) return;
    const int n0 = blockIdx.x * 128;
    TB_PROLOG2
    const uint32_t* Bh = g_bdh + (size_t)e * (FF / 2) * DD;
    const uint32_t* Bl = g_bdl + (size_t)e * (FF / 2) * DD;
    int gi = m0 + am;
    int gir = (gi < count) ? gi : 0;
    const uint32_t* arh = g_abhi + ((size_t)e * TT + gir) * (FF / 2) + aq;
    const uint32_t* arl = g_ablo + ((size_t)e * TT + gir) * (FF / 2) + aq;
    for (int kq0 = 0; kq0 < FF / 2; kq0 += 16) {
        STAGE_ROWS(Ahs, Als, arh, arl, kq0)
        STAGE_B_NN(Bh, Bl, DD, n0, kq0)
        __syncthreads();
        bf16_block_mma(cacc, Ahs, Als, Bhs, Bls, lane, wm, wn);
        __syncthreads();
    }
    int lr = lane >> 2, lc = lane & 3;
    #pragma unroll
    for (int mt = 0; mt < 4; mt++) {
        int r0 = m0 + wm + mt * 16 + lr;
        #pragma unroll
        for (int half = 0; half < 2; half++) {
            int row = r0 + half * 8;
            if (row < count) {
                int entry = g_idxl[e * TT + row];
                float wgt = g_wslot[entry];
                #pragma unroll
                for (int nt = 0; nt < 4; nt++) {
                    int cn = n0 + wn + nt * 8 + lc * 2;
                    size_t cb = (size_t)entry * DD + cn;
                    g_yslot[cb]     = cacc[mt][nt][half * 2] * wgt;
                    g_yslot[cb + 1] = cacc[mt][nt][half * 2 + 1] * wgt;
                }
            }
        }
    }
}

// ---------------- routing (verified) ----------------
__global__ void reset_router_kernel() {
    if (threadIdx.x < NE) { g_counts[threadIdx.x] = 0; g_probsum[threadIdx.x] = 0.f; }
}
__global__ void reset_aux_kernel() { g_aux = 0.f; }

__global__ void router_kernel(const float* __restrict__ X, const float* __restrict__ RW) {
    int n = blockIdx.x, tid = threadIdx.x;
    const float* xr = X + (size_t)n * DD;
    float p[NE];
    #pragma unroll
    for (int e = 0; e < NE; e++) p[e] = 0.f;
    for (int d = tid; d < DD; d += 256) {
        float xv = xr[d];
        #pragma unroll
        for (int e = 0; e < NE; e++) p[e] += xv * RW[d * NE + e];
    }
    #pragma unroll
    for (int e = 0; e < NE; e++)
        #pragma unroll
        for (int off = 16; off; off >>= 1) p[e] += __shfl_down_sync(0xffffffffu, p[e], off);
    __shared__ float sred[8][NE];
    int warp = tid >> 5, lane = tid & 31;
    if (lane == 0)
        #pragma unroll
        for (int e = 0; e < NE; e++) sred[warp][e] = p[e];
    __syncthreads();
    if (tid == 0) {
        float lg[NE];
        #pragma unroll
        for (int e = 0; e < NE; e++) {
            float s = 0.f;
            #pragma unroll
            for (int w = 0; w < 8; w++) s += sred[w][e];
            lg[e] = s;
        }
        float mx = lg[0];
        #pragma unroll
        for (int e = 1; e < NE; e++) mx = fmaxf(mx, lg[e]);
        float pb[NE], sum = 0.f;
        #pragma unroll
        for (int e = 0; e < NE; e++) { pb[e] = expf(lg[e] - mx); sum += pb[e]; }
        float isum = 1.f / sum;
        #pragma unroll
        for (int e = 0; e < NE; e++) pb[e] *= isum;
        int e1 = 0;
        #pragma unroll
        for (int e = 1; e < NE; e++) if (pb[e] > pb[e1]) e1 = e;
        int e2 = (e1 == 0) ? 1 : 0;
        #pragma unroll
        for (int e = 0; e < NE; e++) if (e != e1 && pb[e] > pb[e2]) e2 = e;
        float s2 = pb[e1] + pb[e2];
        g_wslot[2 * n]     = pb[e1] / s2;
        g_wslot[2 * n + 1] = pb[e2] / s2;
        int p1 = atomicAdd(&g_counts[e1], 1); g_idxl[e1 * TT + p1] = (n << 1);
        int p2 = atomicAdd(&g_counts[e2], 1); g_idxl[e2 * TT + p2] = (n << 1) | 1;
        #pragma unroll
        for (int e = 0; e < NE; e++) atomicAdd(&g_probsum[e], pb[e]);
    }
}

__global__ void aux_kernel() {
    float s = 0.f;
    #pragma unroll
    for (int e = 0; e < NE; e++) s += g_probsum[e] * (float)g_counts[e];
    g_aux += (float)NE * s / ((float)TT * (float)TT);
}

__global__ void combine_kernel(float* __restrict__ x) {
    int n = blockIdx.x;
    for (int d = threadIdx.x; d < DD; d += 256)
        x[(size_t)n * DD + d] += g_yslot[(size_t)(2 * n) * DD + d] +
                                 g_yslot[(size_t)(2 * n + 1) * DD + d];
}

__global__ void write_aux_kernel(float* __restrict__ out) { out[(size_t)TT * VV] = g_aux; }

// ---------------- launch ----------------
extern "C" void kernel_launch(void* const* d_in, const int* in_sizes, int n_in,
                              void* d_out, int out_size) {
    const int*   tokens = (const int*)d_in[0];
    const float* emb    = (const float*)d_in[1];
    const float* n1w    = (const float*)d_in[2];
    const float* n2w    = (const float*)d_in[3];
    const float* wq     = (const float*)d_in[4];
    const float* wk     = (const float*)d_in[5];
    const float* wv     = (const float*)d_in[6];
    const float* wo     = (const float*)d_in[7];
    const float* rw     = (const float*)d_in[8];
    const float* wg     = (const float*)d_in[9];
    const float* wu     = (const float*)d_in[10];
    const float* wd     = (const float*)d_in[11];
    const float* now    = (const float*)d_in[12];
    float* out = (float*)d_out;

    float *px, *ph, *pq, *pk, *pv;
    uint32_t *phh, *phl, *pebh, *pebl;
    uint32_t *pbqh, *pbql, *pbkh, *pbkl, *pbvh, *pbvl, *pboh, *pbol;
    uint32_t *pbuh, *pbul, *pbgh, *pbgl, *pbdh, *pbdl;
    cudaGetSymbolAddress((void**)&px, g_x);
    cudaGetSymbolAddress((void**)&ph, g_h);
    cudaGetSymbolAddress((void**)&pq, g_q);
    cudaGetSymbolAddress((void**)&pk, g_k);
    cudaGetSymbolAddress((void**)&pv, g_v);
    cudaGetSymbolAddress((void**)&phh, g_hhi);
    cudaGetSymbolAddress((void**)&phl, g_hlo);
    cudaGetSymbolAddress((void**)&pebh, g_ebh);
    cudaGetSymbolAddress((void**)&pebl, g_ebl);
    cudaGetSymbolAddress((void**)&pbqh, g_bqh);
    cudaGetSymbolAddress((void**)&pbql, g_bql);
    cudaGetSymbolAddress((void**)&pbkh, g_bkh);
    cudaGetSymbolAddress((void**)&pbkl, g_bkl);
    cudaGetSymbolAddress((void**)&pbvh, g_bvh);
    cudaGetSymbolAddress((void**)&pbvl, g_bvl);
    cudaGetSymbolAddress((void**)&pboh, g_boh);
    cudaGetSymbolAddress((void**)&pbol, g_bol);
    cudaGetSymbolAddress((void**)&pbuh, g_buh);
    cudaGetSymbolAddress((void**)&pbul, g_bul);
    cudaGetSymbolAddress((void**)&pbgh, g_bgh);
    cudaGetSymbolAddress((void**)&pbgl, g_bgl);
    cudaGetSymbolAddress((void**)&pbdh, g_bdh);
    cudaGetSymbolAddress((void**)&pbdl, g_bdl);
    uint32_t *pahi, *palo;
    cudaGetSymbolAddress((void**)&pahi, g_ahi);
    cudaGetSymbolAddress((void**)&palo, g_alo);

    embed_kernel<<<TT * DD / 256, 256>>>(tokens, emb, px);
    rope_table_kernel<<<TT * 32 / 256, 256>>>();
    reset_aux_kernel<<<1, 1>>>();
    {   // emb planes (lm_head B operand), once
        long total = (long)VV * (DD / 2);
        convert_rows_kernel<<<(int)((total + 255) / 256), 256>>>(emb, pebh, pebl, DD / 2, total);
    }

    for (int l = 0; l < 2; l++) {
        rmsnorm_kernel<<<TT, 256>>>(px, n1w + (size_t)l * DD, ph, phh, phl);
        {
            long t1 = (long)(DD / 2) * NH * HD;
            convert_nn_kernel<<<(int)((t1 + 255) / 256), 256>>>(
                wq + (size_t)l * DD * NH * HD, pbqh, pbql, DD, NH * HD, t1);
            long t2 = (long)(DD / 2) * NKV * HD;
            convert_nn_kernel<<<(int)((t2 + 255) / 256), 256>>>(
                wk + (size_t)l * DD * NKV * HD, pbkh, pbkl, DD, NKV * HD, t2);
            convert_nn_kernel<<<(int)((t2 + 255) / 256), 256>>>(
                wv + (size_t)l * DD * NKV * HD, pbvh, pbvl, DD, NKV * HD, t2);
            long t3 = (long)(NH * HD / 2) * DD;
            convert_nn_kernel<<<(int)((t3 + 255) / 256), 256>>>(
                wo + (size_t)l * NH * HD * DD, pboh, pbol, NH * HD, DD, t3);
        }
        tgemm_nn_kernel<false><<<dim3((NH * HD) / 128, TT / 128), 256>>>(
            phh, phl, pbqh, pbql, pq, TT, NH * HD, DD);
        tgemm_nn_kernel<false><<<dim3((NKV * HD) / 128, TT / 128), 256>>>(
            phh, phl, pbkh, pbkl, pk, TT, NKV * HD, DD);
        tgemm_nn_kernel<false><<<dim3((NKV * HD) / 128, TT / 128), 256>>>(
            phh, phl, pbvh, pbvl, pv, TT, NKV * HD, DD);
        attn_flash_kernel<<<dim3(TT / 128, NH), 128>>>(pq, pk, pv);
        tgemm_nn_kernel<true><<<dim3(DD / 128, TT / 128), 256>>>(
            pahi, palo, pboh, pbol, px, TT, DD, NH * HD);

        rmsnorm_kernel<<<TT, 256>>>(px, n2w + (size_t)l * DD, ph, phh, phl);
        reset_router_kernel<<<1, 32>>>();
        router_kernel<<<TT, 256>>>(ph, rw + (size_t)l * DD * NE);
        aux_kernel<<<1, 1>>>();
        {
            long tm = (long)NE * (DD / 2) * FF;
            convert_nn_kernel<<<(int)((tm + 255) / 256), 256>>>(
                wu + (size_t)l * NE * DD * FF, pbuh, pbul, DD, FF, tm);
            convert_nn_kernel<<<(int)((tm + 255) / 256), 256>>>(
                wg + (size_t)l * NE * DD * FF, pbgh, pbgl, DD, FF, tm);
            long td = (long)NE * (FF / 2) * DD;
            convert_nn_kernel<<<(int)((td + 255) / 256), 256>>>(
                wd + (size_t)l * NE * FF * DD, pbdh, pbdl, FF, DD, td);
        }
        tmoe_up_kernel<<<dim3(FF / 128, TT / 128, NE), 256>>>();
        tmoe_gate_kernel<<<dim3(FF / 128, TT / 128, NE), 256>>>();
        tmoe_down_kernel<<<dim3(DD / 128, TT / 128, NE), 256>>>();
        combine_kernel<<<TT, 256>>>(px);
    }

    rmsnorm_kernel<<<TT, 256>>>(px, now, ph, phh, phl);
    tgemm_nt_kernel<<<dim3(VV / 128, TT / 128), 256>>>(phh, phl, pebh, pebl, out, TT, VV, DD);
    if (out_size > TT * VV) write_aux_kernel<<<1, 1>>>(out);
}